// round 16
// baseline (speedup 1.0000x reference)
#include <cuda_runtime.h>
#include <cuda_fp16.h>
#include <cstdint>

// Problem constants
#define BB   2
#define MM   2048
#define NN   2048
#define DMOD 1024
#define NH   16
#define DK   64

#define KW2  2048                         // weight region width [Whi|Wlo]
#define AS2 ((size_t)(BB * MM) * DMOD)    // A (hi-only) region elems
#define WS2 ((size_t)DMOD * KW2)          // W region elems

// Scratch (device globals: allocation-free rule)
__device__ unsigned char g_mask[BB * (size_t)MM * NN];
__device__ int g_mask_kind;
__device__ __half g_A2[3 * ((size_t)(BB * MM) * DMOD)];      // 25 MB
__device__ __half g_W2[3 * ((size_t)DMOD * KW2)];            // 12.6 MB
__device__ __half g_Qh[(size_t)BB * MM * DMOD];              // 8.4 MB
__device__ __half g_Kc[(size_t)BB * NH * NN * DK];           // 8.4 MB (Khi only)
__device__ __half g_Vh[(size_t)BB * NH * NN * DK];           // 8.4 MB
__device__ __half g_Vl[(size_t)BB * NH * NN * DK];           // 8.4 MB

// ---------------------------------------------------------------------------
// Helpers (sm_80-era: mma.sync + ldmatrix + cp.async; NO tcgen05)
// ---------------------------------------------------------------------------
__device__ __forceinline__ uint32_t cvta_s(const void* p) {
    uint32_t a;
    asm("{ .reg .u64 t; cvta.to.shared.u64 t, %1; cvt.u32.u64 %0, t; }"
        : "=r"(a) : "l"(p));
    return a;
}

#define LDSM_X4(r0, r1, r2, r3, a)                                            \
    asm volatile("ldmatrix.sync.aligned.m8n8.x4.shared.b16 {%0,%1,%2,%3}, [%4];" \
                 : "=r"(r0), "=r"(r1), "=r"(r2), "=r"(r3) : "r"(a))

#define LDSM_X4_T(r0, r1, r2, r3, a)                                          \
    asm volatile("ldmatrix.sync.aligned.m8n8.x4.trans.shared.b16 {%0,%1,%2,%3}, [%4];" \
                 : "=r"(r0), "=r"(r1), "=r"(r2), "=r"(r3) : "r"(a))

#define MMA_F16(c0, c1, c2, c3, a0, a1, a2, a3, b0, b1)                       \
    asm volatile("mma.sync.aligned.m16n8k16.row.col.f32.f16.f16.f32 "         \
                 "{%0,%1,%2,%3}, {%4,%5,%6,%7}, {%8,%9}, {%0,%1,%2,%3};"      \
                 : "+f"(c0), "+f"(c1), "+f"(c2), "+f"(c3)                     \
                 : "r"(a0), "r"(a1), "r"(a2), "r"(a3), "r"(b0), "r"(b1))

#define CP_ASYNC16(s, g)                                                      \
    asm volatile("cp.async.cg.shared.global [%0], [%1], 16;" :: "r"(s), "l"(g))
#define CP_COMMIT() asm volatile("cp.async.commit_group;" ::: "memory")
#define CP_WAIT0()  asm volatile("cp.async.wait_group 0;" ::: "memory")
#define CP_WAIT2()  asm volatile("cp.async.wait_group 2;" ::: "memory")

__device__ __forceinline__ uint32_t pack_hf2(float a, float b) {
    __half2 h = __floats2half2_rn(a, b);
    return *(uint32_t*)&h;
}
__device__ __forceinline__ void split2h(float a, float b, uint32_t& h, uint32_t& l) {
    __half ha = __float2half_rn(a), hb = __float2half_rn(b);
    __half2 hh = __halves2half2(ha, hb);
    h = *(uint32_t*)&hh;
    l = pack_hf2(a - __half2float(ha), b - __half2float(hb));
}

// ---------------------------------------------------------------------------
// Mask dtype detection + conversion (known-good)
// ---------------------------------------------------------------------------
__global__ void detect_mask(const unsigned int* __restrict__ w) {
    __shared__ int s_not_int, s_not_float;
    if (threadIdx.x == 0) { s_not_int = 0; s_not_float = 0; }
    __syncthreads();
    int li = 0, lf = 0;
    for (int i = threadIdx.x; i < 65536; i += blockDim.x) {
        unsigned int x = w[i];
        if (x > 1u) li = 1;
        if (x != 0u && x != 0x3F800000u) lf = 1;
    }
    if (li) atomicOr(&s_not_int, 1);
    if (lf) atomicOr(&s_not_float, 1);
    __syncthreads();
    if (threadIdx.x == 0) {
        if (!s_not_int)        g_mask_kind = 1;
        else if (!s_not_float) g_mask_kind = 2;
        else                   g_mask_kind = 0;
    }
}

__global__ void convert_mask(const void* __restrict__ m) {
    size_t i = (size_t)blockIdx.x * blockDim.x + threadIdx.x;
    const size_t total = (size_t)BB * MM * NN / 4;
    if (i >= total) return;
    int kind = g_mask_kind;
    uchar4 o;
    if (kind == 1) {
        int4 v = ((const int4*)m)[i];
        o = make_uchar4(v.x != 0, v.y != 0, v.z != 0, v.w != 0);
    } else if (kind == 2) {
        float4 v = ((const float4*)m)[i];
        o = make_uchar4(v.x != 0.f, v.y != 0.f, v.z != 0.f, v.w != 0.f);
    } else {
        unsigned int v = ((const unsigned int*)m)[i];
        o = make_uchar4((v & 0xffu) != 0, ((v >> 8) & 0xffu) != 0,
                        ((v >> 16) & 0xffu) != 0, (v >> 24) != 0);
    }
    ((uchar4*)g_mask)[i] = o;
}

// ---------------------------------------------------------------------------
// Splits (fp16): act -> hi only [r][1024]; wgt -> [Whi|Wlo] [r][2048]
// ---------------------------------------------------------------------------
__global__ void split_act(const float* __restrict__ X, __half* __restrict__ O) {
    size_t i = (size_t)blockIdx.x * blockDim.x + threadIdx.x;
    const size_t NG = (size_t)(BB * MM) * DMOD / 8;
    if (i >= NG) return;
    int r = (int)(i >> 7);
    int c = (int)(i & 127) << 3;
    const float4* xp = (const float4*)(X + ((size_t)r << 10) + c);
    float4 x0 = xp[0], x1 = xp[1];
    uint4 HI;
    HI.x = pack_hf2(x0.x, x0.y);
    HI.y = pack_hf2(x0.z, x0.w);
    HI.z = pack_hf2(x1.x, x1.y);
    HI.w = pack_hf2(x1.z, x1.w);
    *(uint4*)(O + ((size_t)r << 10) + c) = HI;
}

__global__ void split_wgt(const float* __restrict__ W, __half* __restrict__ O) {
    size_t i = (size_t)blockIdx.x * blockDim.x + threadIdx.x;
    const size_t NG = (size_t)DMOD * DMOD / 8;
    if (i >= NG) return;
    int r = (int)(i >> 7);
    int c = (int)(i & 127) << 3;
    const float4* xp = (const float4*)(W + ((size_t)r << 10) + c);
    float4 x0 = xp[0], x1 = xp[1];
    uint4 HI, LO;
    split2h(x0.x, x0.y, HI.x, LO.x);
    split2h(x0.z, x0.w, HI.y, LO.y);
    split2h(x1.x, x1.y, HI.z, LO.z);
    split2h(x1.z, x1.w, HI.w, LO.w);
    __half* base = O + (size_t)r * KW2 + c;
    *(uint4*)(base)        = HI;
    *(uint4*)(base + 1024) = LO;
}

// ---------------------------------------------------------------------------
// HMMA fp16 GEMM, 4-stage cp.async pipeline.
// fin=0: z=0 -> Qh (fp16, K=1024 hi-only W)
//        z=1 -> Kc (head-major Khi, K=1024 hi-only W)
//        z=2 -> Vh/Vl (split, K=2048 [Whi|Wlo])
// fin=1: fp32 output to Cout (K=2048).
// ---------------------------------------------------------------------------
#define SROWB  80
#define GSTAGE (128 * SROWB * 2)
#define G_SMEM (4 * GSTAGE)               // 81920 B

__global__ void __launch_bounds__(128, 2) gemm_hmma(
        const uint4* __restrict__ A2,
        const uint4* __restrict__ B2,
        float* __restrict__ Cout,
        __half* __restrict__ Qh,
        __half* __restrict__ Kc,
        __half* __restrict__ Vh,
        __half* __restrict__ Vl,
        int fin) {
    extern __shared__ char gsm[];
    const uint32_t sb = cvta_s(gsm);

    const int t = threadIdx.x;
    const int lane = t & 31, wid = t >> 5;
    const int m0 = blockIdx.y * 128, n0 = blockIdx.x * 128;
    const int z = blockIdx.z;
    const int wm = (wid & 1) * 64, wn = (wid >> 1) * 64;
    const int g = lane >> 2, tq = lane & 3;
    const int nkc = (fin || z == 2) ? 64 : 32;

    const uint4* Az = A2 + (size_t)z * (AS2 / 8);
    const uint4* Bz = B2 + (size_t)z * (WS2 / 8);

    const uint4* arow = Az + (size_t)(m0 + t) * 128;
    const uint4* brow = Bz + (size_t)(n0 + t) * 256;
    const int swz = (t >> 3) & 3;
    const uint32_t strow = (uint32_t)(t * SROWB);

    auto load_stage = [&](int kc, int stg) {
        const uint32_t sa = sb + (uint32_t)stg * GSTAGE;
        const uint32_t sbB = sa + 128 * SROWB;
        const uint4* ap = arow + (kc & 31) * 4;
        const uint4* bp = brow + kc * 4;
#pragma unroll
        for (int j = 0; j < 4; j++) {
            uint32_t off = strow + (uint32_t)((j ^ swz) << 4);
            CP_ASYNC16(sa + off, (const char*)(ap + j));
            CP_ASYNC16(sbB + off, (const char*)(bp + j));
        }
    };

    load_stage(0, 0); CP_COMMIT();
    load_stage(1, 1); CP_COMMIT();
    load_stage(2, 2); CP_COMMIT();

    float c[4][8][4];
#pragma unroll
    for (int i = 0; i < 4; i++)
#pragma unroll
        for (int j = 0; j < 8; j++)
#pragma unroll
            for (int q = 0; q < 4; q++) c[i][j][q] = 0.f;

    const int jj = lane >> 3;
    const int r8 = lane & 7;

    for (int kc = 0; kc < nkc; kc++) {
        CP_WAIT2();
        __syncthreads();
        if (kc < nkc - 3) load_stage(kc + 3, (kc + 3) & 3);
        CP_COMMIT();

        const char* Ab = gsm + (kc & 3) * GSTAGE;
        const char* Bb = Ab + 128 * SROWB;
#pragma unroll
        for (int ks = 0; ks < 2; ks++) {
            const int ku = ks * 2;
            uint32_t a[4][4], b[8][2];
#pragma unroll
            for (int mt = 0; mt < 4; mt++) {
                int r = wm + mt * 16 + ((jj & 1) << 3) + r8;
                int u = (ku + (jj >> 1)) ^ ((r >> 3) & 3);
                uint32_t ad = cvta_s(Ab + r * SROWB + (u << 4));
                LDSM_X4(a[mt][0], a[mt][1], a[mt][2], a[mt][3], ad);
            }
#pragma unroll
            for (int np = 0; np < 4; np++) {
                int r = wn + np * 16 + ((jj >> 1) << 3) + r8;
                int u = (ku + (jj & 1)) ^ ((r >> 3) & 3);
                uint32_t ad = cvta_s(Bb + r * SROWB + (u << 4));
                LDSM_X4(b[np * 2][0], b[np * 2][1], b[np * 2 + 1][0], b[np * 2 + 1][1], ad);
            }
#pragma unroll
            for (int mt = 0; mt < 4; mt++)
#pragma unroll
                for (int nt = 0; nt < 8; nt++)
                    MMA_F16(c[mt][nt][0], c[mt][nt][1], c[mt][nt][2], c[mt][nt][3],
                            a[mt][0], a[mt][1], a[mt][2], a[mt][3],
                            b[nt][0], b[nt][1]);
        }
    }

    // Epilogue: route by mode
    if (fin) {
#pragma unroll
        for (int mt = 0; mt < 4; mt++) {
            int row = m0 + wm + mt * 16 + g;
#pragma unroll
            for (int nt = 0; nt < 8; nt++) {
                int col = n0 + wn + nt * 8 + tq * 2;
                *(float2*)&Cout[(size_t)row * DMOD + col] =
                    make_float2(c[mt][nt][0], c[mt][nt][1]);
                *(float2*)&Cout[(size_t)(row + 8) * DMOD + col] =
                    make_float2(c[mt][nt][2], c[mt][nt][3]);
            }
        }
    } else if (z == 0) {
#pragma unroll
        for (int mt = 0; mt < 4; mt++) {
            int row = m0 + wm + mt * 16 + g;
#pragma unroll
            for (int nt = 0; nt < 8; nt++) {
                int col = n0 + wn + nt * 8 + tq * 2;
                *(uint32_t*)&Qh[(size_t)row * DMOD + col] = pack_hf2(c[mt][nt][0], c[mt][nt][1]);
                *(uint32_t*)&Qh[(size_t)(row + 8) * DMOD + col] = pack_hf2(c[mt][nt][2], c[mt][nt][3]);
            }
        }
    } else if (z == 1) {
        // Kc: head-major Khi only
#pragma unroll
        for (int mt = 0; mt < 4; mt++) {
            int row = m0 + wm + mt * 16 + g;
#pragma unroll
            for (int nt = 0; nt < 8; nt++) {
                int col = n0 + wn + nt * 8 + tq * 2;
                int h_ = col >> 6, d_ = col & 63;
                {
                    int b_ = row >> 11, n_ = row & 2047;
                    size_t hb = ((size_t)(b_ * NH + h_)) * NN + n_;
                    *(uint32_t*)&Kc[hb * DK + d_] = pack_hf2(c[mt][nt][0], c[mt][nt][1]);
                }
                {
                    int row2 = row + 8;
                    int b_ = row2 >> 11, n_ = row2 & 2047;
                    size_t hb = ((size_t)(b_ * NH + h_)) * NN + n_;
                    *(uint32_t*)&Kc[hb * DK + d_] = pack_hf2(c[mt][nt][2], c[mt][nt][3]);
                }
            }
        }
    } else {
        // Vh/Vl: head-major split
#pragma unroll
        for (int mt = 0; mt < 4; mt++) {
            int row = m0 + wm + mt * 16 + g;
#pragma unroll
            for (int nt = 0; nt < 8; nt++) {
                int col = n0 + wn + nt * 8 + tq * 2;
                int h_ = col >> 6, d_ = col & 63;
                {
                    int b_ = row >> 11, n_ = row & 2047;
                    size_t hb = ((size_t)(b_ * NH + h_)) * NN + n_;
                    uint32_t hi, lo;
                    split2h(c[mt][nt][0], c[mt][nt][1], hi, lo);
                    *(uint32_t*)&Vh[hb * DK + d_] = hi;
                    *(uint32_t*)&Vl[hb * DK + d_] = lo;
                }
                {
                    int row2 = row + 8;
                    int b_ = row2 >> 11, n_ = row2 & 2047;
                    size_t hb = ((size_t)(b_ * NH + h_)) * NN + n_;
                    uint32_t hi, lo;
                    split2h(c[mt][nt][2], c[mt][nt][3], hi, lo);
                    *(uint32_t*)&Vh[hb * DK + d_] = hi;
                    *(uint32_t*)&Vl[hb * DK + d_] = lo;
                }
            }
        }
    }
}

// ---------------------------------------------------------------------------
// HMMA fp16 flash attention: Qhi x Khi (K=64); Phi x (Vhi + Vlo).
// 2-stage cp.async pipeline, 2 CTAs/SM. Writes fp16 ctx-hi.
// ---------------------------------------------------------------------------
#define OFF_KC  0                   // [64][144B]
#define OFF_VH  9216                // [64][144B]
#define OFF_VL  18432               // [64][144B]
#define OFF_MSK 27648               // [128][64B]
#define BUFSZ   35840
#define A2_SMEM (2 * BUFSZ)         // 71680

__global__ void __launch_bounds__(256, 2) attn_hmma(
        const __half* __restrict__ Qh,
        const __half* __restrict__ Kc,
        const __half* __restrict__ Vh,
        const __half* __restrict__ Vl,
        const unsigned char* __restrict__ mask,
        __half* __restrict__ ctxh) {
    extern __shared__ char sm[];
    const uint32_t sb = cvta_s(sm);

    const int t = threadIdx.x;
    const int lane = t & 31, w = t >> 5;
    const int g = lane >> 2, q = lane & 3;
    const int bh = blockIdx.y;
    const int b = bh >> 4, h = bh & 15;
    const int bh2 = b * NH + h;
    const int m0 = blockIdx.x * 128;
    const int wm = w * 16;

    // ---- Phase 0: copy Qhi tile [128][144B] (overlays buffer 0), pull qf
    {
        const int row = t >> 1;
        const int cb = (t & 1) * 32;
        const uint4* qg = (const uint4*)(Qh + ((size_t)(b * MM + m0 + row)) * DMOD + h * DK + cb);
        char* qs = sm + row * 144 + cb * 2;
#pragma unroll
        for (int i = 0; i < 4; i++)
            *(uint4*)(qs + 16 * i) = qg[i];
    }
    __syncthreads();

    uint32_t qf[4][4];
    {
        const int mt_ = lane >> 3, r8_ = lane & 7;
#pragma unroll
        for (int kp = 0; kp < 4; kp++) {
            uint32_t ad = sb + (uint32_t)((wm + (mt_ & 1) * 8 + r8_) * 144
                                          + (kp * 16 + (mt_ >> 1) * 8) * 2);
            LDSM_X4(qf[kp][0], qf[kp][1], qf[kp][2], qf[kp][3], ad);
        }
    }
    __syncthreads();

    // tile loader: 8 cp.async x 16B per thread
    auto load_tile = [&](int itn, uint32_t bufb) {
        const int n0g = itn * 64;
        const uint32_t sdst = sb + bufb;
        const char* kgb = (const char*)(Kc + ((size_t)bh2 * NN + n0g) * DK);
        const char* vhb = (const char*)(Vh + ((size_t)bh2 * NN + n0g) * DK);
        const char* vlb = (const char*)(Vl + ((size_t)bh2 * NN + n0g) * DK);
#pragma unroll
        for (int i = 0; i < 2; i++) {
            int e = t + i * 256;
            int row = e >> 3, cc = e & 7;
            CP_ASYNC16(sdst + OFF_KC + row * 144 + cc * 16, kgb + row * 128 + cc * 16);
            CP_ASYNC16(sdst + OFF_VH + row * 144 + cc * 16, vhb + row * 128 + cc * 16);
            CP_ASYNC16(sdst + OFF_VL + row * 144 + cc * 16, vlb + row * 128 + cc * 16);
        }
        const char* mb = (const char*)(mask + ((size_t)(b * MM + m0)) * NN + n0g);
#pragma unroll
        for (int i = 0; i < 2; i++) {
            int e = t + i * 256;
            int row = e >> 2, cc = e & 3;
            CP_ASYNC16(sdst + OFF_MSK + row * 64 + cc * 16, mb + (size_t)row * NN + cc * 16);
        }
    };

    float O[8][4];
#pragma unroll
    for (int i = 0; i < 8; i++)
#pragma unroll
        for (int j = 0; j < 4; j++) O[i][j] = 0.f;
    float mrow0 = -1e30f, mrow1 = -1e30f, lrow0 = 0.f, lrow1 = 0.f;

    const int mt = lane >> 3, r8 = lane & 7;

    load_tile(0, 0);
    CP_COMMIT();

    for (int it = 0; it < 32; it++) {
        const uint32_t bufb = (uint32_t)(it & 1) * BUFSZ;
        CP_WAIT0();
        __syncthreads();
        if (it < 31) {
            load_tile(it + 1, (uint32_t)((it + 1) & 1) * BUFSZ);
            CP_COMMIT();
        }

        // ---- S = Qhi @ Khi^T  (K=64: 2 chunks of 32)
        float S[8][4];
#pragma unroll
        for (int i = 0; i < 8; i++)
#pragma unroll
            for (int j = 0; j < 4; j++) S[i][j] = 0.f;

#pragma unroll
        for (int kp = 0; kp < 2; kp++) {
            const int qi = kp * 2;
#pragma unroll
            for (int nt = 0; nt < 8; nt++) {
                uint32_t b0, b1, b2, b3;
                uint32_t ad = sb + bufb + OFF_KC + (uint32_t)((nt * 8 + r8) * 144
                                                             + (kp * 32 + mt * 8) * 2);
                LDSM_X4(b0, b1, b2, b3, ad);
                MMA_F16(S[nt][0], S[nt][1], S[nt][2], S[nt][3],
                        qf[qi][0], qf[qi][1], qf[qi][2], qf[qi][3], b0, b1);
                MMA_F16(S[nt][0], S[nt][1], S[nt][2], S[nt][3],
                        qf[qi + 1][0], qf[qi + 1][1], qf[qi + 1][2], qf[qi + 1][3], b2, b3);
            }
        }

        // ---- mask + scale (matches ref: (mask ? -1e9 : s) * 0.125)
        const char* mbuf = sm + bufb + OFF_MSK;
#pragma unroll
        for (int nt = 0; nt < 8; nt++) {
            unsigned short mA = *(const unsigned short*)(mbuf + (wm + g) * 64 + nt * 8 + 2 * q);
            unsigned short mB = *(const unsigned short*)(mbuf + (wm + g + 8) * 64 + nt * 8 + 2 * q);
            S[nt][0] = (mA & 0xff) ? -1.25e8f : S[nt][0] * 0.125f;
            S[nt][1] = (mA >> 8)   ? -1.25e8f : S[nt][1] * 0.125f;
            S[nt][2] = (mB & 0xff) ? -1.25e8f : S[nt][2] * 0.125f;
            S[nt][3] = (mB >> 8)   ? -1.25e8f : S[nt][3] * 0.125f;
        }

        // ---- online softmax
        float mx0 = -1e30f, mx1 = -1e30f;
#pragma unroll
        for (int nt = 0; nt < 8; nt++) {
            mx0 = fmaxf(mx0, fmaxf(S[nt][0], S[nt][1]));
            mx1 = fmaxf(mx1, fmaxf(S[nt][2], S[nt][3]));
        }
        mx0 = fmaxf(mx0, __shfl_xor_sync(0xffffffffu, mx0, 1));
        mx0 = fmaxf(mx0, __shfl_xor_sync(0xffffffffu, mx0, 2));
        mx1 = fmaxf(mx1, __shfl_xor_sync(0xffffffffu, mx1, 1));
        mx1 = fmaxf(mx1, __shfl_xor_sync(0xffffffffu, mx1, 2));
        const float nm0 = fmaxf(mrow0, mx0);
        const float nm1 = fmaxf(mrow1, mx1);
        const float c0 = __expf(mrow0 - nm0);
        const float c1 = __expf(mrow1 - nm1);
        mrow0 = nm0; mrow1 = nm1;

        float s0 = 0.f, s1 = 0.f;
        uint32_t pa[4][4];
#pragma unroll
        for (int nt = 0; nt < 8; nt++) {
            float p0 = __expf(S[nt][0] - nm0);
            float p1 = __expf(S[nt][1] - nm0);
            float p2 = __expf(S[nt][2] - nm1);
            float p3 = __expf(S[nt][3] - nm1);
            s0 += p0 + p1;
            s1 += p2 + p3;
            const int ks = nt >> 1;
            const int hv = (nt & 1) * 2;
            pa[ks][hv]     = pack_hf2(p0, p1);
            pa[ks][hv + 1] = pack_hf2(p2, p3);
        }
        s0 += __shfl_xor_sync(0xffffffffu, s0, 1);
        s0 += __shfl_xor_sync(0xffffffffu, s0, 2);
        s1 += __shfl_xor_sync(0xffffffffu, s1, 1);
        s1 += __shfl_xor_sync(0xffffffffu, s1, 2);
        lrow0 = lrow0 * c0 + s0;
        lrow1 = lrow1 * c1 + s1;

#pragma unroll
        for (int dt = 0; dt < 8; dt++) {
            O[dt][0] *= c0; O[dt][1] *= c0;
            O[dt][2] *= c1; O[dt][3] *= c1;
        }

        // ---- O += Phi @ (Vhi + Vlo): interleaved loads
#pragma unroll
        for (int ks = 0; ks < 4; ks++) {
            const uint32_t vrow = (uint32_t)(ks * 16 + (mt & 1) * 8 + r8);
#pragma unroll
            for (int dp = 0; dp < 4; dp++) {
                const uint32_t vcol = (uint32_t)(dp * 16 + (mt >> 1) * 8);
                uint32_t v0, v1, v2, v3;
                LDSM_X4_T(v0, v1, v2, v3, sb + bufb + OFF_VH + vrow * 144 + vcol * 2);
                MMA_F16(O[2*dp][0], O[2*dp][1], O[2*dp][2], O[2*dp][3],
                        pa[ks][0], pa[ks][1], pa[ks][2], pa[ks][3], v0, v1);
                MMA_F16(O[2*dp+1][0], O[2*dp+1][1], O[2*dp+1][2], O[2*dp+1][3],
                        pa[ks][0], pa[ks][1], pa[ks][2], pa[ks][3], v2, v3);
                LDSM_X4_T(v0, v1, v2, v3, sb + bufb + OFF_VL + vrow * 144 + vcol * 2);
                MMA_F16(O[2*dp][0], O[2*dp][1], O[2*dp][2], O[2*dp][3],
                        pa[ks][0], pa[ks][1], pa[ks][2], pa[ks][3], v0, v1);
                MMA_F16(O[2*dp+1][0], O[2*dp+1][1], O[2*dp+1][2], O[2*dp+1][3],
                        pa[ks][0], pa[ks][1], pa[ks][2], pa[ks][3], v2, v3);
            }
        }
    }

    // ---- epilogue: write fp16 ctx-hi (A-operand of the output projection)
    const float inv0 = 1.0f / lrow0;
    const float inv1 = 1.0f / lrow1;
    const int row0 = m0 + wm + g;
#pragma unroll
    for (int dt = 0; dt < 8; dt++) {
        int col = h * DK + dt * 8 + 2 * q;
        *(uint32_t*)&ctxh[((size_t)(b * MM + row0)) * DMOD + col] =
            pack_hf2(O[dt][0] * inv0, O[dt][1] * inv0);
        *(uint32_t*)&ctxh[((size_t)(b * MM + row0 + 8)) * DMOD + col] =
            pack_hf2(O[dt][2] * inv1, O[dt][3] * inv1);
    }
}

// ---------------------------------------------------------------------------
extern "C" void kernel_launch(void* const* d_in, const int* in_sizes, int n_in,
                              void* d_out, int out_size) {
    const float* q  = (const float*)d_in[0];
    const float* k  = (const float*)d_in[1];
    const float* v  = (const float*)d_in[2];
    const void*  mask_raw = d_in[3];
    const float* Wq = (const float*)d_in[4];
    const float* Wk = (const float*)d_in[5];
    const float* Wv = (const float*)d_in[6];
    const float* Wo = (const float*)d_in[7];
    float* out = (float*)d_out;

    void *mask_, *A2_, *W2_, *Qh_, *Kc_, *Vh_, *Vl_;
    cudaGetSymbolAddress(&mask_, g_mask);
    cudaGetSymbolAddress(&A2_,  g_A2);
    cudaGetSymbolAddress(&W2_,  g_W2);
    cudaGetSymbolAddress(&Qh_,  g_Qh);
    cudaGetSymbolAddress(&Kc_,  g_Kc);
    cudaGetSymbolAddress(&Vh_,  g_Vh);
    cudaGetSymbolAddress(&Vl_,  g_Vl);
    unsigned char* mask = (unsigned char*)mask_;
    __half* A2 = (__half*)A2_;
    __half* W2 = (__half*)W2_;
    __half* Qh = (__half*)Qh_;
    __half* Kc = (__half*)Kc_;
    __half* Vh = (__half*)Vh_;
    __half* Vl = (__half*)Vl_;

    cudaFuncSetAttribute(attn_hmma,
                         cudaFuncAttributeMaxDynamicSharedMemorySize, A2_SMEM);
    cudaFuncSetAttribute(gemm_hmma,
                         cudaFuncAttributeMaxDynamicSharedMemorySize, G_SMEM);

    // Normalize mask dtype -> uint8
    detect_mask<<<1, 1024>>>((const unsigned int*)mask_raw);
    convert_mask<<<(unsigned)(((size_t)BB * MM * NN / 4 + 255) / 256), 256>>>(mask_raw);

    const unsigned actg = (unsigned)(((size_t)(BB * MM) * DMOD / 8 + 255) / 256);
    const unsigned wgtg = (unsigned)(((size_t)DMOD * DMOD / 8 + 255) / 256);

    // Stage the three input projections, run as one batched GEMM launch that
    // writes fp16 consumer formats directly (Qh, Kc, Vh/Vl).
    split_act<<<actg, 256>>>(q, A2);
    split_act<<<actg, 256>>>(k, A2 + AS2);
    split_act<<<actg, 256>>>(v, A2 + 2 * AS2);
    split_wgt<<<wgtg, 256>>>(Wq, W2);
    split_wgt<<<wgtg, 256>>>(Wk, W2 + WS2);
    split_wgt<<<wgtg, 256>>>(Wv, W2 + 2 * WS2);

    dim3 gridG3(DMOD / 128, (BB * MM) / 128, 3);        // (8, 32, 3)
    gemm_hmma<<<gridG3, 128, G_SMEM>>>((const uint4*)A2, (const uint4*)W2,
                                       out, Qh, Kc, Vh, Vl, 0);

    // Attention: writes fp16 ctx-hi directly into A2 region 0
    dim3 gridA(MM / 128, BB * NH);                      // (16, 32)
    attn_hmma<<<gridA, 256, A2_SMEM>>>(Qh, Kc, Vh, Vl, mask, A2);

    // out = ctx @ Wo^T (fp32 epilogue, 2-term W)
    split_wgt<<<wgtg, 256>>>(Wo, W2);
    dim3 gridG(DMOD / 128, (BB * MM) / 128, 1);
    gemm_hmma<<<gridG, 128, G_SMEM>>>((const uint4*)A2, (const uint4*)W2,
                                      out, Qh, Kc, Vh, Vl, 1);
}